// round 4
// baseline (speedup 1.0000x reference)
#include <cuda_runtime.h>

#define NB    1024      // batch
#define NS    32        // neighbors per hop
#define DIM   64
#define NREL  237
#define NRELP 238
#define NENTP 14542     // NENT + 1
#define WCS   256       // padded row stride for folded output weights

// ---------------- scratch (device globals; no allocation allowed) ----------
__device__ __align__(16) float g_R[NRELP * DIM];       // relf @ W_agg0 (row 237 = 0)
__device__ __align__(16) float g_S[NENTP * DIM];       // unmasked hop-2 sums per entity
__device__ __align__(16) float g_Wc[2 * DIM * WCS];    // W_agg1 @ W_out halves, padded rows
__device__ __align__(16) float g_W4p[DIM * WCS];       // mW4 padded to 1KB rows
__device__ __align__(16) float g_bc[NREL];             // b_agg1 @ (Wtop+Wbot) + b_out
__device__ __align__(16) float g_A[DIM * DIM];         // W_agg1 @ mW1[0:237]
__device__ __align__(16) float g_d[DIM];               // b_agg1 @ mW1[0:237] + mb1
__device__ __align__(16) float g_pre[2 * NB * DIM];    // masked-mean hidden per side

__device__ __forceinline__ float selu_f(float x) {
    const float sc  = 1.0507009873554805f;
    const float asc = 1.7580993408473766f;   // sc * alpha
    return x > 0.f ? sc * x : asc * expm1f(x);
}

// ---------------- kernel 0: per-launch weight folding ----------------------
__global__ __launch_bounds__(256) void k_fold(
    const float* __restrict__ relf, const float* __restrict__ W0,
    const float* __restrict__ W1,   const float* __restrict__ b1,
    const float* __restrict__ Wout, const float* __restrict__ bout,
    const float* __restrict__ mW1,  const float* __restrict__ mb1,
    const float* __restrict__ mW4)
{
    int bid = blockIdx.x, tid = threadIdx.x;
    if (bid < NRELP) {                       // R = relf @ W_agg0  (row 237 zero)
        if (tid < DIM) {
            float a0 = 0.f, a1 = 0.f, a2 = 0.f, a3 = 0.f;
            if (bid < NREL) {
                #pragma unroll
                for (int k = 0; k < DIM; k += 4) {
                    a0 += relf[bid * DIM + k]     * W0[(k)     * DIM + tid];
                    a1 += relf[bid * DIM + k + 1] * W0[(k + 1) * DIM + tid];
                    a2 += relf[bid * DIM + k + 2] * W0[(k + 2) * DIM + tid];
                    a3 += relf[bid * DIM + k + 3] * W0[(k + 3) * DIM + tid];
                }
            }
            g_R[bid * DIM + tid] = (a0 + a1) + (a2 + a3);
        }
    } else if (bid < NRELP + 128) {          // Wc[s][i][:] = W_agg1[i,:] @ W_out half
        int idx = bid - NRELP;
        int s = idx >> 6, i = idx & 63;
        if (tid < NREL) {
            float a0 = 0.f, a1 = 0.f, a2 = 0.f, a3 = 0.f;
            const float* w1r = W1 + i * NREL;
            const float* wo  = Wout + s * NREL * NREL;
            int k = 0;
            for (; k + 3 < NREL; k += 4) {
                a0 += w1r[k]     * wo[(k)     * NREL + tid];
                a1 += w1r[k + 1] * wo[(k + 1) * NREL + tid];
                a2 += w1r[k + 2] * wo[(k + 2) * NREL + tid];
                a3 += w1r[k + 3] * wo[(k + 3) * NREL + tid];
            }
            for (; k < NREL; k++) a0 += w1r[k] * wo[k * NREL + tid];
            g_Wc[s * DIM * WCS + i * WCS + tid] = (a0 + a1) + (a2 + a3);
        }
    } else if (bid < NRELP + 128 + 64) {     // A[i][:] = W_agg1[i,:] @ mW1[0:237]
        int i = bid - NRELP - 128;
        if (tid < DIM) {
            float a0 = 0.f, a1 = 0.f, a2 = 0.f, a3 = 0.f;
            const float* w1r = W1 + i * NREL;
            int k = 0;
            for (; k + 3 < NREL; k += 4) {
                a0 += w1r[k]     * mW1[(k)     * DIM + tid];
                a1 += w1r[k + 1] * mW1[(k + 1) * DIM + tid];
                a2 += w1r[k + 2] * mW1[(k + 2) * DIM + tid];
                a3 += w1r[k + 3] * mW1[(k + 3) * DIM + tid];
            }
            for (; k < NREL; k++) a0 += w1r[k] * mW1[k * DIM + tid];
            g_A[i * DIM + tid] = (a0 + a1) + (a2 + a3);
        }
    } else if (bid < NRELP + 128 + 64 + 64) { // padded copy of mW4
        int kk = bid - (NRELP + 128 + 64);
        if (tid < NREL) g_W4p[kk * WCS + tid] = mW4[kk * NREL + tid];
    } else {                                 // bias vectors
        if (tid < NREL) {
            float acc = bout[tid];
            for (int k = 0; k < NREL; k++)
                acc += b1[k] * (Wout[k * NREL + tid] + Wout[(k + NREL) * NREL + tid]);
            g_bc[tid] = acc;
        }
        if (tid < DIM) {
            float acc = mb1[tid];
            for (int k = 0; k < NREL; k++)
                acc += b1[k] * mW1[k * DIM + tid];
            g_d[tid] = acc;
        }
    }
}

// ---------------- kernel 1: unmasked hop-2 sums per entity -----------------
__global__ __launch_bounds__(256) void k_S(
    const int* __restrict__ entity2edges, const int* __restrict__ edge2relation)
{
    int w = threadIdx.x >> 5, lane = threadIdx.x & 31;
    int ent = blockIdx.x * 8 + w;
    if (ent >= NENTP) return;
    int e = entity2edges[ent * NS + lane];        // coalesced
    int r = edge2relation[e];                     // scattered gather
    const float2* R2 = (const float2*)g_R;
    float a0 = 0.f, a1 = 0.f;
    #pragma unroll
    for (int j = 0; j < 32; j++) {
        int rj = __shfl_sync(0xffffffffu, r, j);
        float2 f = R2[rj * 32 + lane];
        a0 += f.x; a1 += f.y;
    }
    ((float2*)g_S)[ent * 32 + lane] = make_float2(a0, a1);
}

// ---------------- kernel 2: per-(b, side) aggregation via S correction -----
__global__ __launch_bounds__(256) void k_side(
    const int* __restrict__ entity_pairs, const int* __restrict__ train_edges,
    const int* __restrict__ entity2edges, const int* __restrict__ edge2entities,
    const int* __restrict__ edge2relation, const float* __restrict__ b_agg0)
{
    int w = threadIdx.x >> 5, lane = threadIdx.x & 31;
    int task = blockIdx.x * 8 + w;               // [0, 2*NB)
    int b = task >> 1, side = task & 1;

    int te  = train_edges[b];
    int ent = entity_pairs[b * 2 + side];
    int e1   = entity2edges[ent * NS + lane];    // coalesced
    float m1 = (e1 != te) ? 1.f : 0.f;
    int r1   = edge2relation[e1];                // scattered
    int ent2 = edge2entities[e1];                // scattered
    int r_te = edge2relation[te];

    const float2* R2 = (const float2*)g_R;
    const float2* S2 = (const float2*)g_S;
    float2 corr = R2[r_te * 32 + lane];
    float bias0 = b_agg0[2 * lane], bias1 = b_agg0[2 * lane + 1];
    float p0 = 0.f, p1 = 0.f;

    #pragma unroll 4
    for (int si = 0; si < 32; si++) {
        int entj = __shfl_sync(0xffffffffu, ent2, si);
        int e2   = entity2edges[entj * NS + lane];   // coalesced 128B
        unsigned bal = __ballot_sync(0xffffffffu, e2 == te);
        float cnt = (float)__popc(bal);
        float2 S  = S2[entj * 32 + lane];
        int r1j   = __shfl_sync(0xffffffffu, r1, si);
        float2 e  = R2[r1j * 32 + lane];
        float h0 = fmaxf((S.x - cnt * corr.x) * (1.f / NS) + e.x + bias0, 0.f);
        float h1 = fmaxf((S.y - cnt * corr.y) * (1.f / NS) + e.y + bias1, 0.f);
        float mj = __shfl_sync(0xffffffffu, m1, si);
        p0 += mj * h0; p1 += mj * h1;
    }
    ((float2*)g_pre)[(side * NB + b) * 32 + lane] =
        make_float2(p0 * (1.f / NS), p1 * (1.f / NS));
}

// ---------------- kernel 3: fused output GEMM + MLP, 4 batch rows / block --
__global__ __launch_bounds__(256) void k_tail(
    const float* __restrict__ t_in, const float* __restrict__ eps,
    const float* __restrict__ mW1,
    const float* __restrict__ mW2, const float* __restrict__ mb2,
    const float* __restrict__ mW3, const float* __restrict__ mb3,
    const float* __restrict__ mb4,
    float* __restrict__ out)
{
    __shared__ __align__(16) float s_q0[DIM * 4];   // [k][b]
    __shared__ __align__(16) float s_q1[DIM * 4];
    __shared__ __align__(16) float s_pm[DIM * 4];
    __shared__ __align__(16) float s_ha[DIM * 4];
    __shared__ __align__(16) float s_hb[DIM * 4];
    __shared__ float s_eps[4][240];
    __shared__ float s_out[4][240];

    int tid = threadIdx.x;
    int b0  = blockIdx.x * 4;
    int j = tid & 63, i = tid >> 6;     // (b=i, dim=j); b constant per warp

    // ---- stage ----
    float ti  = t_in[b0 + i];
    float q0v = g_pre[(b0 + i) * DIM + j];
    float q1v = g_pre[(NB + b0 + i) * DIM + j];
    s_q0[j * 4 + i] = q0v;
    s_q1[j * 4 + i] = q1v;
    s_pm[j * 4 + i] = (1.f - ti) * q0v + ti * q1v;
    #pragma unroll
    for (int bb = 0; bb < 4; bb++)
        if (tid < NREL) s_eps[bb][tid] = eps[(b0 + bb) * NREL + tid];
    __syncthreads();

    // ---- folded "output" GEMM: out_o = bc + q0@Wc0 + q1@Wc1 (237 threads, 4 b-accs)
    if (tid < NREL) {
        float bc = g_bc[tid];
        float a0 = bc, a1 = bc, a2 = bc, a3 = bc;
        const float* Wc0 = g_Wc + tid;
        const float* Wc1 = g_Wc + DIM * WCS + tid;
        const float4* q04 = (const float4*)s_q0;
        const float4* q14 = (const float4*)s_q1;
        #pragma unroll 8
        for (int kk = 0; kk < DIM; kk++) {
            float w0 = Wc0[kk * WCS], w1 = Wc1[kk * WCS];
            float4 q0 = q04[kk], q1 = q14[kk];
            a0 += q0.x * w0 + q1.x * w1;
            a1 += q0.y * w0 + q1.y * w1;
            a2 += q0.z * w0 + q1.z * w1;
            a3 += q0.w * w0 + q1.w * w1;
        }
        s_out[0][tid] = a0; s_out[1][tid] = a1;
        s_out[2][tid] = a2; s_out[3][tid] = a3;
    }

    // ---- layer 1 (folded): g = d + t*mW1[237] + pm@A + 0.1*eps@mW1 (all 256 thr)
    {
        float g0 = 0.f, g1 = 0.f, g2 = 0.f, g3 = 0.f;
        #pragma unroll
        for (int kk = 0; kk < DIM; kk += 4) {
            g0 += s_pm[(kk)     * 4 + i] * g_A[(kk)     * DIM + j];
            g1 += s_pm[(kk + 1) * 4 + i] * g_A[(kk + 1) * DIM + j];
            g2 += s_pm[(kk + 2) * 4 + i] * g_A[(kk + 2) * DIM + j];
            g3 += s_pm[(kk + 3) * 4 + i] * g_A[(kk + 3) * DIM + j];
        }
        float e0 = 0.f, e1 = 0.f, e2 = 0.f, e3 = 0.f;
        int kk = 0;
        #pragma unroll 4
        for (; kk + 3 < NREL; kk += 4) {
            e0 += s_eps[i][kk]     * mW1[(kk)     * DIM + j];
            e1 += s_eps[i][kk + 1] * mW1[(kk + 1) * DIM + j];
            e2 += s_eps[i][kk + 2] * mW1[(kk + 2) * DIM + j];
            e3 += s_eps[i][kk + 3] * mW1[(kk + 3) * DIM + j];
        }
        for (; kk < NREL; kk++) e0 += s_eps[i][kk] * mW1[kk * DIM + j];
        float g = g_d[j] + ti * mW1[NREL * DIM + j]
                + ((g0 + g1) + (g2 + g3)) + 0.1f * ((e0 + e1) + (e2 + e3));
        s_ha[j * 4 + i] = selu_f(g);
    }
    __syncthreads();

    // ---- layer 2 ----
    {
        float n0 = 0.f, n1 = 0.f, n2 = 0.f, n3 = 0.f;
        #pragma unroll
        for (int kk = 0; kk < DIM; kk += 4) {
            n0 += s_ha[(kk)     * 4 + i] * mW2[(kk)     * DIM + j];
            n1 += s_ha[(kk + 1) * 4 + i] * mW2[(kk + 1) * DIM + j];
            n2 += s_ha[(kk + 2) * 4 + i] * mW2[(kk + 2) * DIM + j];
            n3 += s_ha[(kk + 3) * 4 + i] * mW2[(kk + 3) * DIM + j];
        }
        s_hb[j * 4 + i] = selu_f(mb2[j] + (n0 + n1) + (n2 + n3));
    }
    __syncthreads();

    // ---- layer 3 (write into s_pm, free after layer 1) ----
    {
        float n0 = 0.f, n1 = 0.f, n2 = 0.f, n3 = 0.f;
        #pragma unroll
        for (int kk = 0; kk < DIM; kk += 4) {
            n0 += s_hb[(kk)     * 4 + i] * mW3[(kk)     * DIM + j];
            n1 += s_hb[(kk + 1) * 4 + i] * mW3[(kk + 1) * DIM + j];
            n2 += s_hb[(kk + 2) * 4 + i] * mW3[(kk + 2) * DIM + j];
            n3 += s_hb[(kk + 3) * 4 + i] * mW3[(kk + 3) * DIM + j];
        }
        s_pm[j * 4 + i] = selu_f(mb3[j] + (n0 + n1) + (n2 + n3));
    }
    __syncthreads();

    // ---- layer 4: vt = h@mW4 + mb4, scores = out_o * vt (237 threads, 4 b-accs)
    if (tid < NREL) {
        float bb4 = mb4[tid];
        float a0 = bb4, a1 = bb4, a2 = bb4, a3 = bb4;
        const float* W4 = g_W4p + tid;
        const float4* h4 = (const float4*)s_pm;
        #pragma unroll 8
        for (int kk = 0; kk < DIM; kk++) {
            float w = W4[kk * WCS];
            float4 h = h4[kk];
            a0 += h.x * w; a1 += h.y * w; a2 += h.z * w; a3 += h.w * w;
        }
        out[(b0 + 0) * NREL + tid] = s_out[0][tid] * a0;
        out[(b0 + 1) * NREL + tid] = s_out[1][tid] * a1;
        out[(b0 + 2) * NREL + tid] = s_out[2][tid] * a2;
        out[(b0 + 3) * NREL + tid] = s_out[3][tid] * a3;
    }
}

// ---------------- launcher --------------------------------------------------
extern "C" void kernel_launch(void* const* d_in, const int* in_sizes, int n_in,
                              void* d_out, int out_size)
{
    const int*   entity_pairs  = (const int*)d_in[0];
    const int*   train_edges   = (const int*)d_in[1];
    // d_in[2] = labels : dead
    const int*   entity2edges  = (const int*)d_in[3];
    const int*   edge2entities = (const int*)d_in[4];
    const int*   edge2relation = (const int*)d_in[5];
    const float* t             = (const float*)d_in[6];
    const float* eps           = (const float*)d_in[7];
    const float* rel_feat      = (const float*)d_in[8];
    const float* W_agg0        = (const float*)d_in[9];
    const float* b_agg0        = (const float*)d_in[10];
    const float* W_agg1        = (const float*)d_in[11];
    const float* b_agg1        = (const float*)d_in[12];
    const float* W_out         = (const float*)d_in[13];
    const float* b_out         = (const float*)d_in[14];
    const float* mW1           = (const float*)d_in[15];
    const float* mb1           = (const float*)d_in[16];
    const float* mW2           = (const float*)d_in[17];
    const float* mb2           = (const float*)d_in[18];
    const float* mW3           = (const float*)d_in[19];
    const float* mb3           = (const float*)d_in[20];
    const float* mW4           = (const float*)d_in[21];
    const float* mb4           = (const float*)d_in[22];
    float* out = (float*)d_out;

    k_fold<<<NRELP + 128 + 64 + 64 + 1, 256>>>(rel_feat, W_agg0, W_agg1, b_agg1,
                                               W_out, b_out, mW1, mb1, mW4);
    k_S<<<(NENTP + 7) / 8, 256>>>(entity2edges, edge2relation);
    k_side<<<(2 * NB) / 8, 256>>>(entity_pairs, train_edges, entity2edges,
                                  edge2entities, edge2relation, b_agg0);
    k_tail<<<NB / 4, 256>>>(t, eps, mW1, mW2, mb2, mW3, mb3, mb4, out);
}

// round 5
// speedup vs baseline: 1.0083x; 1.0083x over previous
#include <cuda_runtime.h>

#define NB    1024      // batch
#define NS    32        // neighbors per hop
#define DIM   64
#define NREL  237
#define NRELP 238
#define NENTP 14542     // NENT + 1
#define WCS   256       // padded row stride for folded output weights

// ---------------- scratch (device globals; no allocation allowed) ----------
__device__ __align__(16) float g_R[NRELP * DIM];       // relf @ W_agg0 (row 237 = 0)
__device__ __align__(16) float g_S[NENTP * DIM];       // unmasked hop-2 sums per entity
__device__ __align__(16) float g_Wc[2 * DIM * WCS];    // W_agg1 @ W_out halves, padded rows
__device__ __align__(16) float g_W4p[DIM * WCS];       // mW4 padded to 1KB rows
__device__ __align__(16) float g_bc[NREL];             // b_agg1 @ (Wtop+Wbot) + b_out
__device__ __align__(16) float g_A[DIM * DIM];         // W_agg1 @ mW1[0:237]
__device__ __align__(16) float g_d[DIM];               // b_agg1 @ mW1[0:237] + mb1
__device__ __align__(16) float g_pre[2 * NB * DIM];    // masked-mean hidden per side

__device__ __forceinline__ float selu_f(float x) {
    const float sc  = 1.0507009873554805f;
    const float asc = 1.7580993408473766f;   // sc * alpha
    return x > 0.f ? sc * x : asc * expm1f(x);
}

// ---------------- kernel 0: per-launch weight folding ----------------------
__global__ __launch_bounds__(256) void k_fold(
    const float* __restrict__ relf, const float* __restrict__ W0,
    const float* __restrict__ W1,   const float* __restrict__ b1,
    const float* __restrict__ Wout, const float* __restrict__ bout,
    const float* __restrict__ mW1,  const float* __restrict__ mb1,
    const float* __restrict__ mW4)
{
    int bid = blockIdx.x, tid = threadIdx.x;
    if (bid < NRELP) {                       // R = relf @ W_agg0  (row 237 zero)
        if (tid < DIM) {
            float a0 = 0.f, a1 = 0.f, a2 = 0.f, a3 = 0.f;
            if (bid < NREL) {
                #pragma unroll
                for (int k = 0; k < DIM; k += 4) {
                    a0 += relf[bid * DIM + k]     * W0[(k)     * DIM + tid];
                    a1 += relf[bid * DIM + k + 1] * W0[(k + 1) * DIM + tid];
                    a2 += relf[bid * DIM + k + 2] * W0[(k + 2) * DIM + tid];
                    a3 += relf[bid * DIM + k + 3] * W0[(k + 3) * DIM + tid];
                }
            }
            g_R[bid * DIM + tid] = (a0 + a1) + (a2 + a3);
        }
    } else if (bid < NRELP + 128) {          // Wc[s][i][:] = W_agg1[i,:] @ W_out half
        int idx = bid - NRELP;
        int s = idx >> 6, i = idx & 63;
        if (tid < NREL) {
            float a0 = 0.f, a1 = 0.f, a2 = 0.f, a3 = 0.f;
            const float* w1r = W1 + i * NREL;
            const float* wo  = Wout + s * NREL * NREL;
            int k = 0;
            for (; k + 3 < NREL; k += 4) {
                a0 += w1r[k]     * wo[(k)     * NREL + tid];
                a1 += w1r[k + 1] * wo[(k + 1) * NREL + tid];
                a2 += w1r[k + 2] * wo[(k + 2) * NREL + tid];
                a3 += w1r[k + 3] * wo[(k + 3) * NREL + tid];
            }
            for (; k < NREL; k++) a0 += w1r[k] * wo[k * NREL + tid];
            g_Wc[s * DIM * WCS + i * WCS + tid] = (a0 + a1) + (a2 + a3);
        }
    } else if (bid < NRELP + 128 + 64) {     // A[i][:] = W_agg1[i,:] @ mW1[0:237]
        int i = bid - NRELP - 128;
        if (tid < DIM) {
            float a0 = 0.f, a1 = 0.f, a2 = 0.f, a3 = 0.f;
            const float* w1r = W1 + i * NREL;
            int k = 0;
            for (; k + 3 < NREL; k += 4) {
                a0 += w1r[k]     * mW1[(k)     * DIM + tid];
                a1 += w1r[k + 1] * mW1[(k + 1) * DIM + tid];
                a2 += w1r[k + 2] * mW1[(k + 2) * DIM + tid];
                a3 += w1r[k + 3] * mW1[(k + 3) * DIM + tid];
            }
            for (; k < NREL; k++) a0 += w1r[k] * mW1[k * DIM + tid];
            g_A[i * DIM + tid] = (a0 + a1) + (a2 + a3);
        }
    } else if (bid < NRELP + 128 + 64 + 64) { // padded copy of mW4
        int kk = bid - (NRELP + 128 + 64);
        if (tid < NREL) g_W4p[kk * WCS + tid] = mW4[kk * NREL + tid];
    } else {                                 // bias vectors
        if (tid < NREL) {
            float acc = bout[tid];
            for (int k = 0; k < NREL; k++)
                acc += b1[k] * (Wout[k * NREL + tid] + Wout[(k + NREL) * NREL + tid]);
            g_bc[tid] = acc;
        }
        if (tid < DIM) {
            float acc = mb1[tid];
            for (int k = 0; k < NREL; k++)
                acc += b1[k] * mW1[k * DIM + tid];
            g_d[tid] = acc;
        }
    }
}

// ---------------- kernel 1: unmasked hop-2 sums per entity -----------------
__global__ __launch_bounds__(256) void k_S(
    const int* __restrict__ entity2edges, const int* __restrict__ edge2relation)
{
    int w = threadIdx.x >> 5, lane = threadIdx.x & 31;
    int ent = blockIdx.x * 8 + w;
    if (ent >= NENTP) return;
    int e = entity2edges[ent * NS + lane];        // coalesced
    int r = edge2relation[e];                     // scattered gather
    const float2* R2 = (const float2*)g_R;
    float a0 = 0.f, a1 = 0.f;
    #pragma unroll
    for (int j = 0; j < 32; j++) {
        int rj = __shfl_sync(0xffffffffu, r, j);
        float2 f = R2[rj * 32 + lane];
        a0 += f.x; a1 += f.y;
    }
    ((float2*)g_S)[ent * 32 + lane] = make_float2(a0, a1);
}

// ---------------- kernel 2: per-(b, side) aggregation via S correction -----
__global__ __launch_bounds__(256) void k_side(
    const int* __restrict__ entity_pairs, const int* __restrict__ train_edges,
    const int* __restrict__ entity2edges, const int* __restrict__ edge2entities,
    const int* __restrict__ edge2relation, const float* __restrict__ b_agg0)
{
    int w = threadIdx.x >> 5, lane = threadIdx.x & 31;
    int task = blockIdx.x * 8 + w;               // [0, 2*NB)
    int b = task >> 1, side = task & 1;

    int te  = train_edges[b];
    int ent = entity_pairs[b * 2 + side];
    int e1   = entity2edges[ent * NS + lane];    // coalesced
    float m1 = (e1 != te) ? 1.f : 0.f;
    int r1   = edge2relation[e1];                // scattered
    int ent2 = edge2entities[e1];                // scattered
    int r_te = edge2relation[te];

    const float2* R2 = (const float2*)g_R;
    const float2* S2 = (const float2*)g_S;
    float2 corr = R2[r_te * 32 + lane];
    float bias0 = b_agg0[2 * lane], bias1 = b_agg0[2 * lane + 1];
    float p0 = 0.f, p1 = 0.f;

    #pragma unroll 4
    for (int si = 0; si < 32; si++) {
        int entj = __shfl_sync(0xffffffffu, ent2, si);
        int e2   = entity2edges[entj * NS + lane];   // coalesced 128B
        unsigned bal = __ballot_sync(0xffffffffu, e2 == te);
        float cnt = (float)__popc(bal);
        float2 S  = S2[entj * 32 + lane];
        int r1j   = __shfl_sync(0xffffffffu, r1, si);
        float2 e  = R2[r1j * 32 + lane];
        float h0 = fmaxf((S.x - cnt * corr.x) * (1.f / NS) + e.x + bias0, 0.f);
        float h1 = fmaxf((S.y - cnt * corr.y) * (1.f / NS) + e.y + bias1, 0.f);
        float mj = __shfl_sync(0xffffffffu, m1, si);
        p0 += mj * h0; p1 += mj * h1;
    }
    ((float2*)g_pre)[(side * NB + b) * 32 + lane] =
        make_float2(p0 * (1.f / NS), p1 * (1.f / NS));
}

// ---------------- kernel 3: fused output GEMM + MLP, 4 batch rows / block --
__global__ __launch_bounds__(256) void k_tail(
    const float* __restrict__ t_in, const float* __restrict__ eps,
    const float* __restrict__ mW1,
    const float* __restrict__ mW2, const float* __restrict__ mb2,
    const float* __restrict__ mW3, const float* __restrict__ mb3,
    const float* __restrict__ mb4,
    float* __restrict__ out)
{
    __shared__ __align__(16) float s_q0[DIM * 4];   // [k][b]
    __shared__ __align__(16) float s_q1[DIM * 4];
    __shared__ __align__(16) float s_pm[DIM * 4];
    __shared__ __align__(16) float s_ha[DIM * 4];
    __shared__ __align__(16) float s_hb[DIM * 4];
    __shared__ float s_eps[4][240];
    __shared__ float s_out[4][240];

    int tid = threadIdx.x;
    int b0  = blockIdx.x * 4;
    int j = tid & 63, i = tid >> 6;     // (b=i, dim=j); b constant per warp

    // ---- stage ----
    float ti  = t_in[b0 + i];
    float q0v = g_pre[(b0 + i) * DIM + j];
    float q1v = g_pre[(NB + b0 + i) * DIM + j];
    s_q0[j * 4 + i] = q0v;
    s_q1[j * 4 + i] = q1v;
    s_pm[j * 4 + i] = (1.f - ti) * q0v + ti * q1v;
    #pragma unroll
    for (int bb = 0; bb < 4; bb++)
        if (tid < NREL) s_eps[bb][tid] = eps[(b0 + bb) * NREL + tid];
    __syncthreads();

    // ---- folded "output" GEMM: out_o = bc + q0@Wc0 + q1@Wc1 (237 threads, 4 b-accs)
    if (tid < NREL) {
        float bc = g_bc[tid];
        float a0 = bc, a1 = bc, a2 = bc, a3 = bc;
        const float* Wc0 = g_Wc + tid;
        const float* Wc1 = g_Wc + DIM * WCS + tid;
        const float4* q04 = (const float4*)s_q0;
        const float4* q14 = (const float4*)s_q1;
        #pragma unroll 8
        for (int kk = 0; kk < DIM; kk++) {
            float w0 = Wc0[kk * WCS], w1 = Wc1[kk * WCS];
            float4 q0 = q04[kk], q1 = q14[kk];
            a0 += q0.x * w0 + q1.x * w1;
            a1 += q0.y * w0 + q1.y * w1;
            a2 += q0.z * w0 + q1.z * w1;
            a3 += q0.w * w0 + q1.w * w1;
        }
        s_out[0][tid] = a0; s_out[1][tid] = a1;
        s_out[2][tid] = a2; s_out[3][tid] = a3;
    }

    // ---- layer 1 (folded): g = d + t*mW1[237] + pm@A + 0.1*eps@mW1 (all 256 thr)
    {
        float g0 = 0.f, g1 = 0.f, g2 = 0.f, g3 = 0.f;
        #pragma unroll
        for (int kk = 0; kk < DIM; kk += 4) {
            g0 += s_pm[(kk)     * 4 + i] * g_A[(kk)     * DIM + j];
            g1 += s_pm[(kk + 1) * 4 + i] * g_A[(kk + 1) * DIM + j];
            g2 += s_pm[(kk + 2) * 4 + i] * g_A[(kk + 2) * DIM + j];
            g3 += s_pm[(kk + 3) * 4 + i] * g_A[(kk + 3) * DIM + j];
        }
        float e0 = 0.f, e1 = 0.f, e2 = 0.f, e3 = 0.f;
        int kk = 0;
        #pragma unroll 4
        for (; kk + 3 < NREL; kk += 4) {
            e0 += s_eps[i][kk]     * mW1[(kk)     * DIM + j];
            e1 += s_eps[i][kk + 1] * mW1[(kk + 1) * DIM + j];
            e2 += s_eps[i][kk + 2] * mW1[(kk + 2) * DIM + j];
            e3 += s_eps[i][kk + 3] * mW1[(kk + 3) * DIM + j];
        }
        for (; kk < NREL; kk++) e0 += s_eps[i][kk] * mW1[kk * DIM + j];
        float g = g_d[j] + ti * mW1[NREL * DIM + j]
                + ((g0 + g1) + (g2 + g3)) + 0.1f * ((e0 + e1) + (e2 + e3));
        s_ha[j * 4 + i] = selu_f(g);
    }
    __syncthreads();

    // ---- layer 2 ----
    {
        float n0 = 0.f, n1 = 0.f, n2 = 0.f, n3 = 0.f;
        #pragma unroll
        for (int kk = 0; kk < DIM; kk += 4) {
            n0 += s_ha[(kk)     * 4 + i] * mW2[(kk)     * DIM + j];
            n1 += s_ha[(kk + 1) * 4 + i] * mW2[(kk + 1) * DIM + j];
            n2 += s_ha[(kk + 2) * 4 + i] * mW2[(kk + 2) * DIM + j];
            n3 += s_ha[(kk + 3) * 4 + i] * mW2[(kk + 3) * DIM + j];
        }
        s_hb[j * 4 + i] = selu_f(mb2[j] + (n0 + n1) + (n2 + n3));
    }
    __syncthreads();

    // ---- layer 3 (write into s_pm, free after layer 1) ----
    {
        float n0 = 0.f, n1 = 0.f, n2 = 0.f, n3 = 0.f;
        #pragma unroll
        for (int kk = 0; kk < DIM; kk += 4) {
            n0 += s_hb[(kk)     * 4 + i] * mW3[(kk)     * DIM + j];
            n1 += s_hb[(kk + 1) * 4 + i] * mW3[(kk + 1) * DIM + j];
            n2 += s_hb[(kk + 2) * 4 + i] * mW3[(kk + 2) * DIM + j];
            n3 += s_hb[(kk + 3) * 4 + i] * mW3[(kk + 3) * DIM + j];
        }
        s_pm[j * 4 + i] = selu_f(mb3[j] + (n0 + n1) + (n2 + n3));
    }
    __syncthreads();

    // ---- layer 4: vt = h@mW4 + mb4, scores = out_o * vt (237 threads, 4 b-accs)
    if (tid < NREL) {
        float bb4 = mb4[tid];
        float a0 = bb4, a1 = bb4, a2 = bb4, a3 = bb4;
        const float* W4 = g_W4p + tid;
        const float4* h4 = (const float4*)s_pm;
        #pragma unroll 8
        for (int kk = 0; kk < DIM; kk++) {
            float w = W4[kk * WCS];
            float4 h = h4[kk];
            a0 += h.x * w; a1 += h.y * w; a2 += h.z * w; a3 += h.w * w;
        }
        out[(b0 + 0) * NREL + tid] = s_out[0][tid] * a0;
        out[(b0 + 1) * NREL + tid] = s_out[1][tid] * a1;
        out[(b0 + 2) * NREL + tid] = s_out[2][tid] * a2;
        out[(b0 + 3) * NREL + tid] = s_out[3][tid] * a3;
    }
}

// ---------------- launcher --------------------------------------------------
extern "C" void kernel_launch(void* const* d_in, const int* in_sizes, int n_in,
                              void* d_out, int out_size)
{
    const int*   entity_pairs  = (const int*)d_in[0];
    const int*   train_edges   = (const int*)d_in[1];
    // d_in[2] = labels : dead
    const int*   entity2edges  = (const int*)d_in[3];
    const int*   edge2entities = (const int*)d_in[4];
    const int*   edge2relation = (const int*)d_in[5];
    const float* t             = (const float*)d_in[6];
    const float* eps           = (const float*)d_in[7];
    const float* rel_feat      = (const float*)d_in[8];
    const float* W_agg0        = (const float*)d_in[9];
    const float* b_agg0        = (const float*)d_in[10];
    const float* W_agg1        = (const float*)d_in[11];
    const float* b_agg1        = (const float*)d_in[12];
    const float* W_out         = (const float*)d_in[13];
    const float* b_out         = (const float*)d_in[14];
    const float* mW1           = (const float*)d_in[15];
    const float* mb1           = (const float*)d_in[16];
    const float* mW2           = (const float*)d_in[17];
    const float* mb2           = (const float*)d_in[18];
    const float* mW3           = (const float*)d_in[19];
    const float* mb3           = (const float*)d_in[20];
    const float* mW4           = (const float*)d_in[21];
    const float* mb4           = (const float*)d_in[22];
    float* out = (float*)d_out;

    k_fold<<<NRELP + 128 + 64 + 64 + 1, 256>>>(rel_feat, W_agg0, W_agg1, b_agg1,
                                               W_out, b_out, mW1, mb1, mW4);
    k_S<<<(NENTP + 7) / 8, 256>>>(entity2edges, edge2relation);
    k_side<<<(2 * NB) / 8, 256>>>(entity_pairs, train_edges, entity2edges,
                                  edge2entities, edge2relation, b_agg0);
    k_tail<<<NB / 4, 256>>>(t, eps, mW1, mW2, mb2, mW3, mb3, mb4, out);
}

// round 6
// speedup vs baseline: 1.0810x; 1.0721x over previous
#include <cuda_runtime.h>

#define NB    1024      // batch
#define NS    32        // neighbors per hop
#define DIM   64
#define NREL  237
#define NRELP 238
#define NENTP 14542     // NENT + 1
#define WCS   256       // padded row stride for folded output weights

// ---------------- scratch (device globals; no allocation allowed) ----------
__device__ __align__(16) float g_R[NRELP * DIM];       // relf @ W_agg0 (row 237 = 0)
__device__ __align__(16) float g_S[NENTP * DIM];       // unmasked hop-2 sums per entity
__device__ __align__(16) float g_Wc[2 * DIM * WCS];    // W_agg1 @ W_out halves, padded rows
__device__ __align__(16) float g_W4p[DIM * WCS];       // mW4 padded to 1KB rows
__device__ __align__(16) float g_bc[NREL];             // b_agg1 @ (Wtop+Wbot) + b_out
__device__ __align__(16) float g_A[DIM * DIM];         // W_agg1 @ mW1[0:237]
__device__ __align__(16) float g_d[DIM];               // b_agg1 @ mW1[0:237] + mb1
__device__ __align__(16) float g_pre[2 * NB * DIM];    // masked-mean hidden per side
__device__ __align__(16) float g_h3[NB * DIM];         // MLP hidden after layer 3

__device__ __forceinline__ float selu_f(float x) {
    const float sc  = 1.0507009873554805f;
    const float asc = 1.7580993408473766f;   // sc * alpha
    return x > 0.f ? sc * x : asc * expm1f(x);
}

// ---------------- kernel 0: per-launch weight folding ----------------------
__global__ __launch_bounds__(256) void k_fold(
    const float* __restrict__ relf, const float* __restrict__ W0,
    const float* __restrict__ W1,   const float* __restrict__ b1,
    const float* __restrict__ Wout, const float* __restrict__ bout,
    const float* __restrict__ mW1,  const float* __restrict__ mb1,
    const float* __restrict__ mW4)
{
    int bid = blockIdx.x, tid = threadIdx.x;
    if (bid < NRELP) {                       // R = relf @ W_agg0  (row 237 zero)
        if (tid < DIM) {
            float a0 = 0.f, a1 = 0.f, a2 = 0.f, a3 = 0.f;
            if (bid < NREL) {
                #pragma unroll
                for (int k = 0; k < DIM; k += 4) {
                    a0 += relf[bid * DIM + k]     * W0[(k)     * DIM + tid];
                    a1 += relf[bid * DIM + k + 1] * W0[(k + 1) * DIM + tid];
                    a2 += relf[bid * DIM + k + 2] * W0[(k + 2) * DIM + tid];
                    a3 += relf[bid * DIM + k + 3] * W0[(k + 3) * DIM + tid];
                }
            }
            g_R[bid * DIM + tid] = (a0 + a1) + (a2 + a3);
        }
    } else if (bid < NRELP + 128) {          // Wc[s][i][:] = W_agg1[i,:] @ W_out half
        int idx = bid - NRELP;
        int s = idx >> 6, i = idx & 63;
        if (tid < NREL) {
            float a0 = 0.f, a1 = 0.f, a2 = 0.f, a3 = 0.f;
            const float* w1r = W1 + i * NREL;
            const float* wo  = Wout + s * NREL * NREL;
            int k = 0;
            for (; k + 3 < NREL; k += 4) {
                a0 += w1r[k]     * wo[(k)     * NREL + tid];
                a1 += w1r[k + 1] * wo[(k + 1) * NREL + tid];
                a2 += w1r[k + 2] * wo[(k + 2) * NREL + tid];
                a3 += w1r[k + 3] * wo[(k + 3) * NREL + tid];
            }
            for (; k < NREL; k++) a0 += w1r[k] * wo[k * NREL + tid];
            g_Wc[s * DIM * WCS + i * WCS + tid] = (a0 + a1) + (a2 + a3);
        }
    } else if (bid < NRELP + 128 + 64) {     // A[i][:] = W_agg1[i,:] @ mW1[0:237]
        int i = bid - NRELP - 128;
        if (tid < DIM) {
            float a0 = 0.f, a1 = 0.f, a2 = 0.f, a3 = 0.f;
            const float* w1r = W1 + i * NREL;
            int k = 0;
            for (; k + 3 < NREL; k += 4) {
                a0 += w1r[k]     * mW1[(k)     * DIM + tid];
                a1 += w1r[k + 1] * mW1[(k + 1) * DIM + tid];
                a2 += w1r[k + 2] * mW1[(k + 2) * DIM + tid];
                a3 += w1r[k + 3] * mW1[(k + 3) * DIM + tid];
            }
            for (; k < NREL; k++) a0 += w1r[k] * mW1[k * DIM + tid];
            g_A[i * DIM + tid] = (a0 + a1) + (a2 + a3);
        }
    } else if (bid < NRELP + 128 + 64 + 64) { // padded copy of mW4
        int kk = bid - (NRELP + 128 + 64);
        if (tid < NREL) g_W4p[kk * WCS + tid] = mW4[kk * NREL + tid];
    } else {                                 // bias vectors
        if (tid < NREL) {
            float acc = bout[tid];
            for (int k = 0; k < NREL; k++)
                acc += b1[k] * (Wout[k * NREL + tid] + Wout[(k + NREL) * NREL + tid]);
            g_bc[tid] = acc;
        }
        if (tid < DIM) {
            float acc = mb1[tid];
            for (int k = 0; k < NREL; k++)
                acc += b1[k] * mW1[k * DIM + tid];
            g_d[tid] = acc;
        }
    }
}

// ---------------- kernel 1: unmasked hop-2 sums per entity -----------------
__global__ __launch_bounds__(256) void k_S(
    const int* __restrict__ entity2edges, const int* __restrict__ edge2relation)
{
    int w = threadIdx.x >> 5, lane = threadIdx.x & 31;
    int ent = blockIdx.x * 8 + w;
    if (ent >= NENTP) return;
    int e = entity2edges[ent * NS + lane];        // coalesced
    int r = edge2relation[e];                     // scattered gather
    const float2* R2 = (const float2*)g_R;
    float a0 = 0.f, a1 = 0.f;
    #pragma unroll
    for (int j = 0; j < 32; j++) {
        int rj = __shfl_sync(0xffffffffu, r, j);
        float2 f = R2[rj * 32 + lane];
        a0 += f.x; a1 += f.y;
    }
    ((float2*)g_S)[ent * 32 + lane] = make_float2(a0, a1);
}

// ---------------- kernel 2: per-(b, side) aggregation via S correction -----
__global__ __launch_bounds__(256) void k_side(
    const int* __restrict__ entity_pairs, const int* __restrict__ train_edges,
    const int* __restrict__ entity2edges, const int* __restrict__ edge2entities,
    const int* __restrict__ edge2relation, const float* __restrict__ b_agg0)
{
    int w = threadIdx.x >> 5, lane = threadIdx.x & 31;
    int task = blockIdx.x * 8 + w;               // [0, 2*NB)
    int b = task >> 1, side = task & 1;

    int te  = train_edges[b];
    int ent = entity_pairs[b * 2 + side];
    int e1   = entity2edges[ent * NS + lane];    // coalesced
    float m1 = (e1 != te) ? 1.f : 0.f;
    int r1   = edge2relation[e1];                // scattered
    int ent2 = edge2entities[e1];                // scattered
    int r_te = edge2relation[te];

    const float2* R2 = (const float2*)g_R;
    const float2* S2 = (const float2*)g_S;
    float2 corr = R2[r_te * 32 + lane];
    float bias0 = b_agg0[2 * lane], bias1 = b_agg0[2 * lane + 1];
    float p0 = 0.f, p1 = 0.f;

    #pragma unroll 4
    for (int si = 0; si < 32; si++) {
        int entj = __shfl_sync(0xffffffffu, ent2, si);
        int e2   = entity2edges[entj * NS + lane];   // coalesced 128B
        unsigned bal = __ballot_sync(0xffffffffu, e2 == te);
        float cnt = (float)__popc(bal);
        float2 S  = S2[entj * 32 + lane];
        int r1j   = __shfl_sync(0xffffffffu, r1, si);
        float2 e  = R2[r1j * 32 + lane];
        float h0 = fmaxf((S.x - cnt * corr.x) * (1.f / NS) + e.x + bias0, 0.f);
        float h1 = fmaxf((S.y - cnt * corr.y) * (1.f / NS) + e.y + bias1, 0.f);
        float mj = __shfl_sync(0xffffffffu, m1, si);
        p0 += mj * h0; p1 += mj * h1;
    }
    ((float2*)g_pre)[(side * NB + b) * 32 + lane] =
        make_float2(p0 * (1.f / NS), p1 * (1.f / NS));
}

// ---------------- kernel 3: MLP layers 1-3 (weights fit L1: ~109KB) --------
// 512 threads: h = k-half (0/1), i = batch-in-block (0-3), j = dim (0-63)
__global__ __launch_bounds__(512) void k_mlp3(
    const float* __restrict__ t_in, const float* __restrict__ eps,
    const float* __restrict__ mW1,
    const float* __restrict__ mW2, const float* __restrict__ mb2,
    const float* __restrict__ mW3, const float* __restrict__ mb3)
{
    __shared__ __align__(16) float s_pm[DIM * 4];   // [kk][b] ; reused as hb
    __shared__ __align__(16) float s_ha[DIM * 4];
    __shared__ float s_eps[4][240];
    __shared__ float s_part[512];

    int tid = threadIdx.x;
    int h = tid >> 8, r = tid & 255;
    int i = r >> 6, j = r & 63;
    int b0 = blockIdx.x * 4;
    float ti = t_in[b0 + i];

    if (h == 0) {
        float q0v = g_pre[(b0 + i) * DIM + j];
        float q1v = g_pre[(NB + b0 + i) * DIM + j];
        s_pm[j * 4 + i] = (1.f - ti) * q0v + ti * q1v;
    }
    #pragma unroll
    for (int bb = 0; bb < 2; bb++) {
        int row = h * 2 + bb;
        if (r < NREL) s_eps[row][r] = eps[(b0 + row) * NREL + r];
    }
    __syncthreads();

    // ---- layer 1 partial: pm@A (32 kk) + 0.1*eps@mW1 (119/118 kk) ----
    {
        int k0 = h * 32;
        float g0 = 0.f, g1 = 0.f, g2 = 0.f, g3 = 0.f;
        #pragma unroll
        for (int kk = k0; kk < k0 + 32; kk += 4) {
            g0 += s_pm[(kk)     * 4 + i] * g_A[(kk)     * DIM + j];
            g1 += s_pm[(kk + 1) * 4 + i] * g_A[(kk + 1) * DIM + j];
            g2 += s_pm[(kk + 2) * 4 + i] * g_A[(kk + 2) * DIM + j];
            g3 += s_pm[(kk + 3) * 4 + i] * g_A[(kk + 3) * DIM + j];
        }
        int eb = h ? 120 : 0, ee = h ? NREL : 120;
        float e0 = 0.f, e1 = 0.f, e2 = 0.f, e3 = 0.f;
        int kk = eb;
        #pragma unroll 4
        for (; kk + 3 < ee; kk += 4) {
            e0 += s_eps[i][kk]     * mW1[(kk)     * DIM + j];
            e1 += s_eps[i][kk + 1] * mW1[(kk + 1) * DIM + j];
            e2 += s_eps[i][kk + 2] * mW1[(kk + 2) * DIM + j];
            e3 += s_eps[i][kk + 3] * mW1[(kk + 3) * DIM + j];
        }
        for (; kk < ee; kk++) e0 += s_eps[i][kk] * mW1[kk * DIM + j];
        float ps = ((g0 + g1) + (g2 + g3)) + 0.1f * ((e0 + e1) + (e2 + e3));
        if (h == 0) ps += g_d[j] + ti * mW1[NREL * DIM + j];
        s_part[tid] = ps;
    }
    __syncthreads();
    if (h == 0) s_ha[j * 4 + i] = selu_f(s_part[tid] + s_part[tid + 256]);
    __syncthreads();

    // ---- layer 2 partial ----
    {
        int k0 = h * 32;
        float n0 = 0.f, n1 = 0.f, n2 = 0.f, n3 = 0.f;
        #pragma unroll
        for (int kk = k0; kk < k0 + 32; kk += 4) {
            n0 += s_ha[(kk)     * 4 + i] * mW2[(kk)     * DIM + j];
            n1 += s_ha[(kk + 1) * 4 + i] * mW2[(kk + 1) * DIM + j];
            n2 += s_ha[(kk + 2) * 4 + i] * mW2[(kk + 2) * DIM + j];
            n3 += s_ha[(kk + 3) * 4 + i] * mW2[(kk + 3) * DIM + j];
        }
        s_part[tid] = (h == 0 ? mb2[j] : 0.f) + (n0 + n1) + (n2 + n3);
    }
    __syncthreads();
    if (h == 0) s_pm[j * 4 + i] = selu_f(s_part[tid] + s_part[tid + 256]);
    __syncthreads();

    // ---- layer 3 partial ----
    {
        int k0 = h * 32;
        float n0 = 0.f, n1 = 0.f, n2 = 0.f, n3 = 0.f;
        #pragma unroll
        for (int kk = k0; kk < k0 + 32; kk += 4) {
            n0 += s_pm[(kk)     * 4 + i] * mW3[(kk)     * DIM + j];
            n1 += s_pm[(kk + 1) * 4 + i] * mW3[(kk + 1) * DIM + j];
            n2 += s_pm[(kk + 2) * 4 + i] * mW3[(kk + 2) * DIM + j];
            n3 += s_pm[(kk + 3) * 4 + i] * mW3[(kk + 3) * DIM + j];
        }
        s_part[tid] = (h == 0 ? mb3[j] : 0.f) + (n0 + n1) + (n2 + n3);
    }
    __syncthreads();
    if (h == 0)
        g_h3[(b0 + i) * DIM + j] = selu_f(s_part[tid] + s_part[tid + 256]);
}

// ---------------- kernel 4: scores (weights fit L1: ~191KB) ---------------
// 512 threads: j = tid&255 (out col, <237 active), h = matrix/k-half selector
__global__ __launch_bounds__(512) void k_score(
    const float* __restrict__ mb4, float* __restrict__ out)
{
    __shared__ __align__(16) float s_q0[DIM * 4];   // [kk][b]
    __shared__ __align__(16) float s_q1[DIM * 4];
    __shared__ __align__(16) float s_h[DIM * 4];
    __shared__ __align__(16) float4 s_po[512];
    __shared__ __align__(16) float4 s_pv[512];

    int tid = threadIdx.x;
    int h = tid >> 8, r = tid & 255;
    int b0 = blockIdx.x * 4;

    {   // stage activations, [kk][b] layout
        int i = r >> 6, kk = r & 63;
        if (h == 0) {
            s_q0[kk * 4 + i] = g_pre[(b0 + i) * DIM + kk];
            s_h [kk * 4 + i] = g_h3[(b0 + i) * DIM + kk];
        } else {
            s_q1[kk * 4 + i] = g_pre[(NB + b0 + i) * DIM + kk];
        }
    }
    __syncthreads();

    int j = r;
    if (j < NREL) {
        // out partial: h=0 -> bc + q0@Wc0 ; h=1 -> q1@Wc1
        float4 ao = make_float4(0.f, 0.f, 0.f, 0.f);
        const float*  W  = g_Wc + h * DIM * WCS + j;
        const float4* q4 = (const float4*)(h ? s_q1 : s_q0);
        #pragma unroll 8
        for (int kk = 0; kk < DIM; kk++) {
            float w = W[kk * WCS];
            float4 q = q4[kk];
            ao.x += q.x * w; ao.y += q.y * w; ao.z += q.z * w; ao.w += q.w * w;
        }
        if (h == 0) {
            float bc = g_bc[j];
            ao.x += bc; ao.y += bc; ao.z += bc; ao.w += bc;
        }
        s_po[tid] = ao;

        // vt partial: h splits kk 0-31 / 32-63 of W4
        float4 av = make_float4(0.f, 0.f, 0.f, 0.f);
        const float*  W4 = g_W4p + j;
        const float4* h4 = (const float4*)s_h;
        int k0 = h * 32;
        #pragma unroll 8
        for (int kk = k0; kk < k0 + 32; kk++) {
            float w = W4[kk * WCS];
            float4 hh = h4[kk];
            av.x += hh.x * w; av.y += hh.y * w; av.z += hh.z * w; av.w += hh.w * w;
        }
        if (h == 0) {
            float m = mb4[j];
            av.x += m; av.y += m; av.z += m; av.w += m;
        }
        s_pv[tid] = av;
    }
    __syncthreads();

    if (h == 0 && j < NREL) {
        float4 o1 = s_po[tid], o2 = s_po[tid + 256];
        float4 v1 = s_pv[tid], v2 = s_pv[tid + 256];
        out[(b0 + 0) * NREL + j] = (o1.x + o2.x) * (v1.x + v2.x);
        out[(b0 + 1) * NREL + j] = (o1.y + o2.y) * (v1.y + v2.y);
        out[(b0 + 2) * NREL + j] = (o1.z + o2.z) * (v1.z + v2.z);
        out[(b0 + 3) * NREL + j] = (o1.w + o2.w) * (v1.w + v2.w);
    }
}

// ---------------- launcher --------------------------------------------------
extern "C" void kernel_launch(void* const* d_in, const int* in_sizes, int n_in,
                              void* d_out, int out_size)
{
    const int*   entity_pairs  = (const int*)d_in[0];
    const int*   train_edges   = (const int*)d_in[1];
    // d_in[2] = labels : dead
    const int*   entity2edges  = (const int*)d_in[3];
    const int*   edge2entities = (const int*)d_in[4];
    const int*   edge2relation = (const int*)d_in[5];
    const float* t             = (const float*)d_in[6];
    const float* eps           = (const float*)d_in[7];
    const float* rel_feat      = (const float*)d_in[8];
    const float* W_agg0        = (const float*)d_in[9];
    const float* b_agg0        = (const float*)d_in[10];
    const float* W_agg1        = (const float*)d_in[11];
    const float* b_agg1        = (const float*)d_in[12];
    const float* W_out         = (const float*)d_in[13];
    const float* b_out         = (const float*)d_in[14];
    const float* mW1           = (const float*)d_in[15];
    const float* mb1           = (const float*)d_in[16];
    const float* mW2           = (const float*)d_in[17];
    const float* mb2           = (const float*)d_in[18];
    const float* mW3           = (const float*)d_in[19];
    const float* mb3           = (const float*)d_in[20];
    const float* mW4           = (const float*)d_in[21];
    const float* mb4           = (const float*)d_in[22];
    float* out = (float*)d_out;

    k_fold<<<NRELP + 128 + 64 + 64 + 1, 256>>>(rel_feat, W_agg0, W_agg1, b_agg1,
                                               W_out, b_out, mW1, mb1, mW4);
    k_S<<<(NENTP + 7) / 8, 256>>>(entity2edges, edge2relation);
    k_side<<<(2 * NB) / 8, 256>>>(entity_pairs, train_edges, entity2edges,
                                  edge2entities, edge2relation, b_agg0);
    k_mlp3<<<NB / 4, 512>>>(t, eps, mW1, mW2, mb2, mW3, mb3);
    k_score<<<NB / 4, 512>>>(mb4, out);
}